// round 2
// baseline (speedup 1.0000x reference)
#include <cuda_runtime.h>
#include <math.h>

#define NSEQ 256
#define TLEN 32
#define MROWS 8192      // NSEQ*TLEN
#define ENCD 200
#define PCTAS 8

// scratch (static device allocations are allowed)
__device__ float g_P  [MROWS * 800];
__device__ float g_Ya [MROWS * ENCD];
__device__ float g_Yb [MROWS * ENCD];
__device__ float g_enc[NSEQ * ENCD];
__device__ float g_stk[NSEQ * ENCD];

__device__ __forceinline__ float sigf(float x) { return 1.0f / (1.0f + expf(-x)); }
// accurate tanh via expf (robust even under fast-math)
__device__ __forceinline__ float tanh_acc(float x) {
    float e = expf(-2.0f * fabsf(x));
    float r = (1.0f - e) / (1.0f + e);
    return x >= 0.0f ? r : -r;
}
__device__ __forceinline__ float ldcg(const float* p) {
    float v; asm volatile("ld.global.cg.f32 %0, [%1];" : "=f"(v) : "l"(p)); return v;
}
__device__ __forceinline__ void stcg(float* p, float v) {
    asm volatile("st.global.cg.f32 [%0], %1;" :: "l"(p), "f"(v));
}

// ---------------------------------------------------------------------------
// P[m][800] = A[row(m)][0:K] @ W[n][0:K]^T + bias[n]
// tok != nullptr -> A row = emb row tok[m] (layer 0 gather)
// BM=64, BN=80, BK=20, 256 threads, 4x5 micro-tile
// ---------------------------------------------------------------------------
__global__ __launch_bounds__(256) void proj_gemm(
    const float* __restrict__ Asrc, const int* __restrict__ tok,
    const float* __restrict__ W, const float* __restrict__ bias,
    float* __restrict__ P, int K)
{
    __shared__ float As[20 * 68];
    __shared__ float Ws[20 * 80];
    __shared__ unsigned long long roff[64];

    const int tid = threadIdx.x;
    const int M0 = blockIdx.x * 64;
    const int N0 = blockIdx.y * 80;

    if (tid < 64) {
        long long o = tok ? (long long)__ldg(&tok[M0 + tid]) * (long long)K
                          : (long long)(M0 + tid) * (long long)K;
        roff[tid] = (unsigned long long)o;
    }
    const int m0 = (tid >> 4) * 4;
    const int n0 = (tid & 15) * 5;

    float acc[4][5];
#pragma unroll
    for (int i = 0; i < 4; i++)
#pragma unroll
        for (int j = 0; j < 5; j++) acc[i][j] = 0.0f;
    __syncthreads();

    for (int kt = 0; kt < K; kt += 20) {
        { // A tile: 64 rows x 20 k, 5 consecutive k per thread
            int i0 = tid * 5;
            int mm = i0 / 20, kk = i0 % 20;
            const float* ap = Asrc + roff[mm] + kt + kk;
#pragma unroll
            for (int q = 0; q < 5; q++) As[(kk + q) * 68 + mm] = ap[q];
        }
        for (int i = tid; i < 1600; i += 256) { // W tile: 80 rows x 20 k
            int nn = i / 20, kk = i % 20;
            Ws[kk * 80 + nn] = __ldg(&W[(size_t)(N0 + nn) * K + kt + kk]);
        }
        __syncthreads();
#pragma unroll
        for (int kk = 0; kk < 20; kk++) {
            float4 a4 = *(const float4*)&As[kk * 68 + m0];
            float a[4] = {a4.x, a4.y, a4.z, a4.w};
            float b[5];
#pragma unroll
            for (int j = 0; j < 5; j++) b[j] = Ws[kk * 80 + n0 + j];
#pragma unroll
            for (int i = 0; i < 4; i++)
#pragma unroll
                for (int j = 0; j < 5; j++) acc[i][j] += a[i] * b[j];
        }
        __syncthreads();
    }
#pragma unroll
    for (int i = 0; i < 4; i++) {
        size_t row = (size_t)(M0 + m0 + i) * 800 + N0 + n0;
#pragma unroll
        for (int j = 0; j < 5; j++)
            P[row + j] = acc[i][j] + __ldg(&bias[N0 + n0 + j]);
    }
}

// ---------------------------------------------------------------------------
// Recurrence: grid (64 seq-groups, 2 dirs), 400 threads (one per gate row).
// Whh (400x100) in smem, h/c in smem, bias already folded into P.
// ---------------------------------------------------------------------------
__global__ __launch_bounds__(400, 1) void lstm_rec(
    const float* __restrict__ P, const float* __restrict__ Whh2, // (2,400,100)
    const int* __restrict__ lengths, float* __restrict__ Y)
{
    extern __shared__ float sm[];
    float* sW = sm;             // 40000
    float* sH = sm + 40000;     // 4*100
    float* sC = sH + 400;       // 4*100
    float* sG = sC + 400;       // 4*400

    const int tid = threadIdx.x;           // 0..399 (gate row)
    const int dir = blockIdx.y;
    const int sq0 = blockIdx.x * 4;

    const float* Wd = Whh2 + dir * 40000;
    for (int i = tid; i < 40000; i += 400) sW[i] = Wd[i];
    for (int i = tid; i < 800; i += 400) sm[40000 + i] = 0.0f; // h,c = 0

    const int sPW = tid / 100;   // pointwise seq
    const int jPW = tid % 100;   // pointwise unit
    const int myLen = __ldg(&lengths[sq0 + sPW]);
    __syncthreads();

    const float4* sW4 = (const float4*)(sW + tid * 100);
    const float4* sH4 = (const float4*)sH;

    for (int st = 0; st < TLEN; st++) {
        int t = dir ? (TLEN - 1 - st) : st;
        float acc0, acc1, acc2, acc3;
        {
            size_t base = ((size_t)sq0 * TLEN + t) * 800 + dir * 400 + tid;
            acc0 = __ldg(&P[base]);
            acc1 = __ldg(&P[base + 1 * TLEN * 800]);
            acc2 = __ldg(&P[base + 2 * TLEN * 800]);
            acc3 = __ldg(&P[base + 3 * TLEN * 800]);
        }
#pragma unroll
        for (int kq = 0; kq < 25; kq++) {
            float4 w = sW4[kq];
            float4 h0 = sH4[kq], h1 = sH4[25 + kq], h2 = sH4[50 + kq], h3 = sH4[75 + kq];
            acc0 += w.x * h0.x + w.y * h0.y + w.z * h0.z + w.w * h0.w;
            acc1 += w.x * h1.x + w.y * h1.y + w.z * h1.z + w.w * h1.w;
            acc2 += w.x * h2.x + w.y * h2.y + w.z * h2.z + w.w * h2.w;
            acc3 += w.x * h3.x + w.y * h3.y + w.z * h3.z + w.w * h3.w;
        }
        sG[tid] = acc0; sG[400 + tid] = acc1; sG[800 + tid] = acc2; sG[1200 + tid] = acc3;
        __syncthreads();
        { // pointwise: thread (sPW, jPW)
            float gi = sG[sPW * 400 + jPW];
            float gf = sG[sPW * 400 + 100 + jPW];
            float gg = sG[sPW * 400 + 200 + jPW];
            float go = sG[sPW * 400 + 300 + jPW];
            float c  = sC[sPW * 100 + jPW];
            float cn = sigf(gf) * c + sigf(gi) * tanh_acc(gg);
            float hn = sigf(go) * tanh_acc(cn);
            float outv = 0.0f;
            if (t < myLen) {
                sC[sPW * 100 + jPW] = cn;
                sH[sPW * 100 + jPW] = hn;
                outv = hn;
            }
            Y[((size_t)(sq0 + sPW) * TLEN + t) * ENCD + dir * 100 + jPW] = outv;
        }
        __syncthreads();
    }
}

// ---------------------------------------------------------------------------
__global__ __launch_bounds__(200) void meanpool(
    const float* __restrict__ Y, const int* __restrict__ lengths,
    float* __restrict__ enc)
{
    int s = blockIdx.x, e = threadIdx.x;
    const float* p = Y + (size_t)s * TLEN * ENCD + e;
    float sum = 0.0f;
#pragma unroll
    for (int t = 0; t < TLEN; t++) sum += p[t * ENCD];
    enc[s * ENCD + e] = sum / (float)__ldg(&lengths[s]);
}

// ---------------------------------------------------------------------------
// Parser: 8-CTA cluster. CTA bid owns units j in [jlo, jlo+JC) (JC = 13 or 12)
// and holds the 5*JC Wt rows needed to produce its (h,c) slice end-to-end.
// Two cluster barriers per step (read-complete / write-complete).
// ---------------------------------------------------------------------------
__global__ __cluster_dims__(PCTAS, 1, 1) __launch_bounds__(256, 1) void parser_kernel(
    const float* __restrict__ missing, const float* __restrict__ Wa,
    const float* __restrict__ ba, const float* __restrict__ Wt,
    const float* __restrict__ bt, float* __restrict__ out)
{
    extern __shared__ float sm[];
    const int bid = blockIdx.x;
    const int tid = threadIdx.x;
    const int JC  = (bid < 4) ? 13 : 12;
    const int jlo = bid * 12 + (bid < 4 ? bid : 4);
    const int NR  = 5 * JC;

    float* sWt   = sm;             // up to 65*204
    float* sXs   = sm + 13260;     // 200  (tree-lstm input [h1,h2])
    float* sFeat = sXs + 200;      // 600
    float* sWa   = sFeat + 600;    // 1200
    float* sBt   = sWa + 1200;     // 68
    float* sMiss = sBt + 68;       // 200
    float* sPart = sMiss + 200;    // 132
    float* sGb   = sPart + 132;    // 68
    float* sSc   = sGb + 68;       // 4

    for (int i = tid; i < NR * 200; i += 256) {
        int r = i / 200, k = i - r * 200;
        int grow = (r / JC) * 100 + jlo + (r % JC);
        sWt[r * 204 + k] = __ldg(&Wt[grow * 200 + k]);
    }
    if (tid < NR) sBt[tid] = __ldg(&bt[(tid / JC) * 100 + jlo + (tid % JC)]);
    for (int i = tid; i < 1200; i += 256) sWa[i] = __ldg(&Wa[i]);
    for (int i = tid; i < 200; i += 256) sMiss[i] = __ldg(&missing[i]);
    const float ba0 = __ldg(&ba[0]), ba1 = __ldg(&ba[1]);
    __syncthreads();

    int sp = 0, bp = 0;
    for (int step = 0; step < 2 * NSEQ - 1; step++) {
        // -- read phase: feat = [s1, s0, b], xs = [h1, h2] --
        int p1 = sp - 2, p0 = sp - 1;
        for (int i = tid; i < 600; i += 256) {
            int seg = i / 200, e = i - seg * 200;
            float v;
            if (seg == 0)      v = (sp >= 2)   ? ldcg(&g_stk[p1 * ENCD + e]) : sMiss[e];
            else if (seg == 1) v = (sp >= 1)   ? ldcg(&g_stk[p0 * ENCD + e]) : sMiss[e];
            else               v = (bp < NSEQ) ? __ldg(&g_enc[bp * ENCD + e]) : sMiss[e];
            sFeat[i] = v;
            if (seg == 0 && e < 100) sXs[e] = v;
            else if (seg == 1 && e < 100) sXs[100 + e] = v;
        }
        __syncthreads();
        asm volatile("barrier.cluster.arrive.aligned;" ::: "memory"); // reads done

        // -- scores (replicated, deterministic) --
        if (tid < 64) {
            int row = tid >> 5, ln = tid & 31;
            float p = 0.0f;
            for (int k = ln; k < 600; k += 32) p += sWa[row * 600 + k] * sFeat[k];
#pragma unroll
            for (int o = 16; o > 0; o >>= 1) p += __shfl_down_sync(0xffffffffu, p, o);
            if (ln == 0) sSc[row] = p + (row ? ba1 : ba0);
        }
        __syncthreads();
        float m0 = (bp < NSEQ) ? sSc[0] : -1e30f;
        float m1 = (sp >= 2)   ? sSc[1] : -1e30f;
        bool is_shift = (m0 >= m1);  // argmax first-index tie-break

        if (!is_shift) { // tree-lstm gate slice: 5*JC rows, 2 threads/row
            if (tid < 2 * NR) {
                int r = tid >> 1, ph = tid & 1;
                const float4* w4 = (const float4*)(sWt + r * 204 + ph * 100);
                const float4* x4 = (const float4*)(sXs + ph * 100);
                float a0 = 0, a1 = 0, a2 = 0, a3 = 0;
#pragma unroll
                for (int q = 0; q < 25; q++) {
                    float4 w = w4[q], x = x4[q];
                    float d = w.x * x.x + w.y * x.y + w.z * x.z + w.w * x.w;
                    if ((q & 3) == 0) a0 += d; else if ((q & 3) == 1) a1 += d;
                    else if ((q & 3) == 2) a2 += d; else a3 += d;
                }
                sPart[tid] = a0 + a1 + a2 + a3;
            }
            __syncthreads();
            if (tid < NR) sGb[tid] = sPart[2 * tid] + sPart[2 * tid + 1] + sBt[tid];
            __syncthreads();
        }

        asm volatile("barrier.cluster.wait.aligned;" ::: "memory"); // all CTAs read

        // -- write phase --
        if (is_shift) {
            int wp = sp; if (wp < 0) wp = 0; if (wp > NSEQ - 1) wp = NSEQ - 1;
            if (tid < 25) stcg(&g_stk[wp * ENCD + bid * 25 + tid],
                               sFeat[400 + bid * 25 + tid]);
        } else {
            int wp = sp - 2; if (wp < 0) wp = 0; if (wp > NSEQ - 1) wp = NSEQ - 1;
            if (tid < JC) {
                float gi = sGb[tid], gf1 = sGb[JC + tid], gf2 = sGb[2 * JC + tid];
                float go = sGb[3 * JC + tid], gu = sGb[4 * JC + tid];
                int j = jlo + tid;
                float c1 = sFeat[100 + j], c2 = sFeat[300 + j];
                float c = sigf(gf1) * c1 + sigf(gf2) * c2 + sigf(gi) * tanh_acc(gu);
                float h = sigf(go) * tanh_acc(c);
                stcg(&g_stk[wp * ENCD + j], h);
                stcg(&g_stk[wp * ENCD + 100 + j], c);
            }
        }
        __threadfence();
        asm volatile("barrier.cluster.arrive.aligned;" ::: "memory");
        asm volatile("barrier.cluster.wait.aligned;" ::: "memory");   // writes visible

        if (is_shift) { sp += 1; bp += 1; } else { sp -= 1; }
    }
    if (bid == 0 && tid < ENCD) out[tid] = ldcg(&g_stk[tid]);
}

// ---------------------------------------------------------------------------
extern "C" void kernel_launch(void* const* d_in, const int* in_sizes, int n_in,
                              void* d_out, int out_size)
{
    const int*   tokens  = (const int*)d_in[0];
    const int*   lengths = (const int*)d_in[1];
    const float* emb     = (const float*)d_in[2];
    const float* Wih0    = (const float*)d_in[3];   // (2,400,300) -> (800,300)
    const float* Whh0    = (const float*)d_in[4];   // (2,400,100)
    const float* b0      = (const float*)d_in[5];   // (800)
    const float* Wih12   = (const float*)d_in[6];   // (2,2,400,200)
    const float* Whh12   = (const float*)d_in[7];   // (2,2,400,100)
    const float* b12     = (const float*)d_in[8];   // (2,2,400)
    const float* missing = (const float*)d_in[9];
    const float* Wa      = (const float*)d_in[10];
    const float* ba      = (const float*)d_in[11];
    const float* Wt      = (const float*)d_in[12];
    const float* bt      = (const float*)d_in[13];
    float* out = (float*)d_out;

    float *P, *Ya, *Yb, *enc;
    cudaGetSymbolAddress((void**)&P,  g_P);
    cudaGetSymbolAddress((void**)&Ya, g_Ya);
    cudaGetSymbolAddress((void**)&Yb, g_Yb);
    cudaGetSymbolAddress((void**)&enc, g_enc);

    const int lstmSmem = (40000 + 400 + 400 + 1600) * 4;   // 169600
    const int parsSmem = 15732 * 4;                         // 62928
    cudaFuncSetAttribute(lstm_rec, cudaFuncAttributeMaxDynamicSharedMemorySize, lstmSmem);
    cudaFuncSetAttribute(parser_kernel, cudaFuncAttributeMaxDynamicSharedMemorySize, parsSmem);

    dim3 gg(128, 10), rg(64, 2);

    // layer 0
    proj_gemm<<<gg, 256>>>(emb, tokens, Wih0, b0, P, 300);
    lstm_rec<<<rg, 400, lstmSmem>>>(P, Whh0, lengths, Ya);
    // layer 1
    proj_gemm<<<gg, 256>>>(Ya, nullptr, Wih12, b12, P, 200);
    lstm_rec<<<rg, 400, lstmSmem>>>(P, Whh12, lengths, Yb);
    // layer 2
    proj_gemm<<<gg, 256>>>(Yb, nullptr, Wih12 + 160000, b12 + 800, P, 200);
    lstm_rec<<<rg, 400, lstmSmem>>>(P, Whh12 + 80000, lengths, Ya);
    // pool + parse
    meanpool<<<NSEQ, 200>>>(Ya, lengths, enc);
    parser_kernel<<<PCTAS, 256, parsSmem>>>(missing, Wa, ba, Wt, bt, out);
}